// round 3
// baseline (speedup 1.0000x reference)
#include <cuda_runtime.h>
#include <cuda_fp16.h>
#include <mma.h>

using namespace nvcuda;

#define BSZ 128
#define TT  128
#define INP 64
#define HID 512
#define G4  2048
#define HB  (BSZ*HID)   // 65536

// ---------------- device state (no allocations allowed) ----------------
__device__ __half g_eWih0[G4*INP];
__device__ __half g_eWhh0[G4*HID];
__device__ __half g_eWih1[G4*HID];
__device__ __half g_eWhh1[G4*HID];
__device__ __half g_dWih0[G4*HID];
__device__ __half g_dWhh0[G4*HID];
__device__ __half g_dWih1[G4*HID];
__device__ __half g_dWhh1[G4*HID];
__device__ __half g_fcW[INP*HID];
__device__ float  g_be0[G4], g_be1[G4], g_bd0[G4], g_bd1[G4];
__device__ __half g_x16[TT*BSZ*INP];
__device__ __half g_h0[2][HB], g_h1[2][HB], g_hd0[2][HB], g_hd1[2][HB];
__device__ float  g_c0[HB], g_c1[HB], g_cd0[HB], g_cd1[HB];
__device__ float  g_gx[BSZ*G4];            // precomputed z @ dWih0^T
__device__ __half g_hs[TT*BSZ*HID];        // decoder layer-1 outputs for FC

// ---------------- prep: fp32->fp16 weights, bias combine, x transpose, zero state ----------------
__global__ void prep_kernel(
    const float* __restrict__ x,
    const float* __restrict__ eWih0, const float* __restrict__ eWhh0,
    const float* __restrict__ ebih0, const float* __restrict__ ebhh0,
    const float* __restrict__ eWih1, const float* __restrict__ eWhh1,
    const float* __restrict__ ebih1, const float* __restrict__ ebhh1,
    const float* __restrict__ dWih0, const float* __restrict__ dWhh0,
    const float* __restrict__ dbih0, const float* __restrict__ dbhh0,
    const float* __restrict__ dWih1, const float* __restrict__ dWhh1,
    const float* __restrict__ dbih1, const float* __restrict__ dbhh1,
    const float* __restrict__ fcW)
{
    const long NP = 9084928;
    long stride = (long)gridDim.x * blockDim.x;
    for (long i = (long)blockIdx.x * blockDim.x + threadIdx.x; i < NP; i += stride) {
        long r = i;
        if (r < 131072)  { g_eWih0[r] = __float2half(eWih0[r]); continue; } r -= 131072;
        if (r < 1048576) { g_eWhh0[r] = __float2half(eWhh0[r]); continue; } r -= 1048576;
        if (r < 1048576) { g_eWih1[r] = __float2half(eWih1[r]); continue; } r -= 1048576;
        if (r < 1048576) { g_eWhh1[r] = __float2half(eWhh1[r]); continue; } r -= 1048576;
        if (r < 1048576) { g_dWih0[r] = __float2half(dWih0[r]); continue; } r -= 1048576;
        if (r < 1048576) { g_dWhh0[r] = __float2half(dWhh0[r]); continue; } r -= 1048576;
        if (r < 1048576) { g_dWih1[r] = __float2half(dWih1[r]); continue; } r -= 1048576;
        if (r < 1048576) { g_dWhh1[r] = __float2half(dWhh1[r]); continue; } r -= 1048576;
        if (r < 32768)   { g_fcW[r]   = __float2half(fcW[r]);   continue; } r -= 32768;
        if (r < 8192) {
            int which = (int)(r >> 11), j = (int)(r & 2047);
            if      (which == 0) g_be0[j] = ebih0[j] + ebhh0[j];
            else if (which == 1) g_be1[j] = ebih1[j] + ebhh1[j];
            else if (which == 2) g_bd0[j] = dbih0[j] + dbhh0[j];
            else                 g_bd1[j] = dbih1[j] + dbhh1[j];
            continue;
        } r -= 8192;
        if (r < 1048576) {  // x [B,T,IN] -> g_x16 [T,B,IN]
            int t = (int)(r >> 13); int rem = (int)(r & 8191);
            int b = rem >> 6; int k = rem & 63;
            g_x16[r] = __float2half(x[(size_t)b * TT * INP + (size_t)t * INP + k]);
            continue;
        } r -= 1048576;
        if (r < 262144) {   // zero initial h (parity-1 buffers read at t=0)
            int which = (int)(r >> 16); int j = (int)(r & 65535);
            __half z = __float2half(0.f);
            if      (which == 0) g_h0[1][j]  = z;
            else if (which == 1) g_h1[1][j]  = z;
            else if (which == 2) g_hd0[1][j] = z;
            else                 g_hd1[1][j] = z;
            continue;
        } r -= 262144;
        {                   // zero c
            int which = (int)(r >> 16); int j = (int)(r & 65535);
            if      (which == 0) g_c0[j]  = 0.f;
            else if (which == 1) g_c1[j]  = 0.f;
            else if (which == 2) g_cd0[j] = 0.f;
            else                 g_cd1[j] = 0.f;
        }
    }
}

// ---------------- LSTM cell (WMMA) ----------------
struct CellDesc { int active; int layer; int t; };

struct CellPtrs {
    const __half* x;   int din;
    const __half* Wih;
    const __half* hin;
    const __half* Whh;
    const float*  bias;
    const float*  gx;
    float*  c;
    __half* hout;
    __half* hsave;
    float*  gout;
};

__device__ __forceinline__ float sigf(float v) { return 1.f / (1.f + __expf(-v)); }

__device__ __forceinline__ void resolve(int layer, int t, CellPtrs& p) {
    p.x = nullptr; p.din = 0; p.Wih = nullptr; p.hin = nullptr; p.Whh = nullptr;
    p.bias = nullptr; p.gx = nullptr; p.c = nullptr; p.hout = nullptr;
    p.hsave = nullptr; p.gout = nullptr;
    int wr = t & 1, rd = (t + 1) & 1;
    switch (layer) {
    case 0: // encoder layer 0, din=64
        p.x = g_x16 + (size_t)t * BSZ * INP; p.din = INP; p.Wih = g_eWih0;
        p.hin = g_h0[rd]; p.Whh = g_eWhh0; p.bias = g_be0;
        p.c = g_c0; p.hout = g_h0[wr]; break;
    case 1: // encoder layer 1
        p.x = g_h0[wr]; p.din = HID; p.Wih = g_eWih1;
        p.hin = g_h1[rd]; p.Whh = g_eWhh1; p.bias = g_be1;
        p.c = g_c1; p.hout = g_h1[wr]; break;
    case 2: // decoder layer 0: constant-input part precomputed in g_gx
        p.gx = g_gx; p.hin = g_hd0[rd]; p.Whh = g_dWhh0; p.bias = g_bd0;
        p.c = g_cd0; p.hout = g_hd0[wr]; break;
    case 3: // decoder layer 1, saves h for FC
        p.x = g_hd0[wr]; p.din = HID; p.Wih = g_dWih1;
        p.hin = g_hd1[rd]; p.Whh = g_dWhh1; p.bias = g_bd1;
        p.c = g_cd1; p.hout = g_hd1[wr];
        p.hsave = g_hs + (size_t)t * BSZ * HID; break;
    case 4: // gx producer: z @ dWih0^T  (z = encoder h1 at t=T-1, parity (T-1)&1 = 1)
        p.x = g_h1[1]; p.din = HID; p.Wih = g_dWih0; p.gout = g_gx; break;
    }
}

__device__ void run_cell(const CellPtrs& p, int lb) {
    // CTA: 64 batch rows (m0) x 16 hidden units (n0), all 4 gates (one per warp)
    int bh = lb >> 5, nc = lb & 31;
    int m0 = bh * 64, n0 = nc * 16;
    int w = threadIdx.x >> 5;           // warp = gate index
    int j0 = w * HID + n0;              // gate-row base in [4H, K] weight

    wmma::fragment<wmma::accumulator, 16, 16, 16, float> acc[4];
#pragma unroll
    for (int mt = 0; mt < 4; mt++) wmma::fill_fragment(acc[mt], 0.f);
    wmma::fragment<wmma::matrix_a, 16, 16, 16, __half, wmma::row_major> af;
    wmma::fragment<wmma::matrix_b, 16, 16, 16, __half, wmma::col_major> bf;

    if (p.x) {
        const __half* Wb = p.Wih + (size_t)j0 * p.din;
        for (int k0 = 0; k0 < p.din; k0 += 16) {
            wmma::load_matrix_sync(bf, Wb + k0, p.din);
#pragma unroll
            for (int mt = 0; mt < 4; mt++) {
                wmma::load_matrix_sync(af, p.x + (size_t)(m0 + mt * 16) * p.din + k0, p.din);
                wmma::mma_sync(acc[mt], af, bf, acc[mt]);
            }
        }
    }
    if (p.hin) {
        const __half* Wb = p.Whh + (size_t)j0 * HID;
        for (int k0 = 0; k0 < HID; k0 += 16) {
            wmma::load_matrix_sync(bf, Wb + k0, HID);
#pragma unroll
            for (int mt = 0; mt < 4; mt++) {
                wmma::load_matrix_sync(af, p.hin + (size_t)(m0 + mt * 16) * HID + k0, HID);
                wmma::mma_sync(acc[mt], af, bf, acc[mt]);
            }
        }
    }

    __shared__ float sm[4][64][16];
#pragma unroll
    for (int mt = 0; mt < 4; mt++)
        wmma::store_matrix_sync(&sm[w][mt * 16][0], acc[mt], 16, wmma::mem_row_major);
    __syncthreads();

    int tid = threadIdx.x;
    if (p.gout) {
        for (int idx = tid; idx < 4096; idx += 128) {
            int g = idx >> 10, r = idx & 1023, m = r >> 4, n = r & 15;
            p.gout[(size_t)(m0 + m) * G4 + g * HID + n0 + n] = sm[g][m][n];
        }
        return;
    }
    for (int idx = tid; idx < 1024; idx += 128) {
        int m = idx >> 4, n = idx & 15;
        int b = m0 + m, u = n0 + n;
        float vi = sm[0][m][n] + p.bias[u];
        float vf = sm[1][m][n] + p.bias[HID + u];
        float vg = sm[2][m][n] + p.bias[2 * HID + u];
        float vo = sm[3][m][n] + p.bias[3 * HID + u];
        if (p.gx) {
            const float* gr = p.gx + (size_t)b * G4;
            vi += gr[u]; vf += gr[HID + u]; vg += gr[2 * HID + u]; vo += gr[3 * HID + u];
        }
        size_t off = (size_t)b * HID + u;
        float co = p.c[off];
        float cn = sigf(vf) * co + sigf(vi) * tanhf(vg);
        float h  = sigf(vo) * tanhf(cn);
        p.c[off] = cn;
        __half hh = __float2half(h);
        p.hout[off] = hh;
        if (p.hsave) p.hsave[off] = hh;
    }
}

// Two wavefronted cells per launch: blocks [0,64) -> a, [64,128) -> b
__global__ __launch_bounds__(128) void cell2_kernel(CellDesc a, CellDesc b) {
    CellDesc d = (blockIdx.x < 64) ? a : b;
    if (!d.active) return;
    int lb = (blockIdx.x < 64) ? blockIdx.x : blockIdx.x - 64;
    CellPtrs p;
    resolve(d.layer, d.t, p);
    run_cell(p, lb);
}

// ---------------- FC head: out[b,t,i] = hs[t,b,:] . fcW[i,:] + fcb[i] ----------------
__global__ __launch_bounds__(128) void fc_kernel(const float* __restrict__ fcb,
                                                 float* __restrict__ out) {
    int m0 = blockIdx.x * 64;           // m = t*B + b, 256 blocks
    int w = threadIdx.x >> 5;           // warp -> output cols [w*16, w*16+16)

    wmma::fragment<wmma::accumulator, 16, 16, 16, float> acc[4];
#pragma unroll
    for (int mt = 0; mt < 4; mt++) wmma::fill_fragment(acc[mt], 0.f);
    wmma::fragment<wmma::matrix_a, 16, 16, 16, __half, wmma::row_major> af;
    wmma::fragment<wmma::matrix_b, 16, 16, 16, __half, wmma::col_major> bf;

    const __half* Wb = g_fcW + (size_t)(w * 16) * HID;
    for (int k0 = 0; k0 < HID; k0 += 16) {
        wmma::load_matrix_sync(bf, Wb + k0, HID);
#pragma unroll
        for (int mt = 0; mt < 4; mt++) {
            wmma::load_matrix_sync(af, g_hs + (size_t)(m0 + mt * 16) * HID + k0, HID);
            wmma::mma_sync(acc[mt], af, bf, acc[mt]);
        }
    }

    __shared__ float sm[64][64];
#pragma unroll
    for (int mt = 0; mt < 4; mt++)
        wmma::store_matrix_sync(&sm[mt * 16][w * 16], acc[mt], 64, wmma::mem_row_major);
    __syncthreads();

    for (int idx = threadIdx.x; idx < 4096; idx += 128) {
        int m = idx >> 6, i = idx & 63;
        int gm = m0 + m;
        int b = gm & (BSZ - 1), t = gm >> 7;
        out[(size_t)b * TT * INP + (size_t)t * INP + i] = sm[m][i] + fcb[i];
    }
}

// ---------------- launch ----------------
extern "C" void kernel_launch(void* const* d_in, const int* in_sizes, int n_in,
                              void* d_out, int out_size) {
    (void)in_sizes; (void)n_in; (void)out_size;
    const float* x      = (const float*)d_in[0];
    const float* eWih0  = (const float*)d_in[1];
    const float* eWhh0  = (const float*)d_in[2];
    const float* ebih0  = (const float*)d_in[3];
    const float* ebhh0  = (const float*)d_in[4];
    const float* eWih1  = (const float*)d_in[5];
    const float* eWhh1  = (const float*)d_in[6];
    const float* ebih1  = (const float*)d_in[7];
    const float* ebhh1  = (const float*)d_in[8];
    const float* dWih0  = (const float*)d_in[9];
    const float* dWhh0  = (const float*)d_in[10];
    const float* dbih0  = (const float*)d_in[11];
    const float* dbhh0  = (const float*)d_in[12];
    const float* dWih1  = (const float*)d_in[13];
    const float* dWhh1  = (const float*)d_in[14];
    const float* dbih1  = (const float*)d_in[15];
    const float* dbhh1  = (const float*)d_in[16];
    const float* fcW    = (const float*)d_in[17];
    const float* fcb    = (const float*)d_in[18];
    float* out = (float*)d_out;

    prep_kernel<<<4096, 256>>>(x, eWih0, eWhh0, ebih0, ebhh0,
                               eWih1, eWhh1, ebih1, ebhh1,
                               dWih0, dWhh0, dbih0, dbhh0,
                               dWih1, dWhh1, dbih1, dbhh1, fcW);

    // Encoder: wavefront (layer0 @ t=s, layer1 @ t=s-1)
    for (int s = 0; s <= TT; ++s) {
        CellDesc a { s < TT ? 1 : 0, 0, s };
        CellDesc b { s >= 1 ? 1 : 0, 1, s - 1 };
        cell2_kernel<<<128, 128>>>(a, b);
    }

    // Precompute z @ dWih0^T (z constant across all decoder steps)
    {
        CellDesc a { 1, 4, 0 };
        CellDesc b { 0, 0, 0 };
        cell2_kernel<<<128, 128>>>(a, b);
    }

    // Decoder: wavefront (layer0 @ t=s, layer1 @ t=s-1)
    for (int s = 0; s <= TT; ++s) {
        CellDesc a { s < TT ? 1 : 0, 2, s };
        CellDesc b { s >= 1 ? 1 : 0, 3, s - 1 };
        cell2_kernel<<<128, 128>>>(a, b);
    }

    fc_kernel<<<256, 128>>>(fcb, out);
}

// round 4
// speedup vs baseline: 2.3877x; 2.3877x over previous
#include <cuda_runtime.h>
#include <cuda_fp16.h>
#include <mma.h>

using namespace nvcuda;

#define BSZ 128
#define TT  128
#define INP 64
#define HID 512
#define G4  2048
#define HB  (BSZ*HID)
#define NCTA 128
#define WLD 528                 // smem weight row stride (halves), padded vs 512
#define SMEM_BYTES 188416       // 2*64*528*2 (weights) + 32768 (smf) + 16384 (smadd) + 4096 (smc)

// ---------------- device state ----------------
__device__ __half g_eWih0[G4*INP];
__device__ __half g_eWhh0[G4*HID];
__device__ __half g_eWih1[G4*HID];
__device__ __half g_eWhh1[G4*HID];
__device__ __half g_dWih0[G4*HID];
__device__ __half g_dWhh0[G4*HID];
__device__ __half g_dWih1[G4*HID];
__device__ __half g_dWhh1[G4*HID];
__device__ __half g_fcW[INP*HID];
__device__ float  g_be0[G4], g_be1[G4], g_bd0[G4], g_bd1[G4];
__device__ __half g_x16[TT*BSZ*INP];
__device__ __half g_h0[2][HB], g_h1[2][HB], g_hd0[2][HB], g_hd1[2][HB];
__device__ float  g_gx[BSZ*G4];
__device__ __half g_hs[TT*BSZ*HID];
__device__ volatile unsigned g_arrive[NCTA];
__device__ volatile unsigned g_gen;

// ---------------- prep ----------------
__global__ void prep_kernel(
    const float* __restrict__ x,
    const float* __restrict__ eWih0, const float* __restrict__ eWhh0,
    const float* __restrict__ ebih0, const float* __restrict__ ebhh0,
    const float* __restrict__ eWih1, const float* __restrict__ eWhh1,
    const float* __restrict__ ebih1, const float* __restrict__ ebhh1,
    const float* __restrict__ dWih0, const float* __restrict__ dWhh0,
    const float* __restrict__ dbih0, const float* __restrict__ dbhh0,
    const float* __restrict__ dWih1, const float* __restrict__ dWhh1,
    const float* __restrict__ dbih1, const float* __restrict__ dbhh1,
    const float* __restrict__ fcW)
{
    const long NP = 8822913;
    long stride = (long)gridDim.x * blockDim.x;
    for (long i = (long)blockIdx.x * blockDim.x + threadIdx.x; i < NP; i += stride) {
        long r = i;
        if (r < 131072)  { g_eWih0[r] = __float2half(eWih0[r]); continue; } r -= 131072;
        if (r < 1048576) { g_eWhh0[r] = __float2half(eWhh0[r]); continue; } r -= 1048576;
        if (r < 1048576) { g_eWih1[r] = __float2half(eWih1[r]); continue; } r -= 1048576;
        if (r < 1048576) { g_eWhh1[r] = __float2half(eWhh1[r]); continue; } r -= 1048576;
        if (r < 1048576) { g_dWih0[r] = __float2half(dWih0[r]); continue; } r -= 1048576;
        if (r < 1048576) { g_dWhh0[r] = __float2half(dWhh0[r]); continue; } r -= 1048576;
        if (r < 1048576) { g_dWih1[r] = __float2half(dWih1[r]); continue; } r -= 1048576;
        if (r < 1048576) { g_dWhh1[r] = __float2half(dWhh1[r]); continue; } r -= 1048576;
        if (r < 32768)   { g_fcW[r]   = __float2half(fcW[r]);   continue; } r -= 32768;
        if (r < 8192) {
            int which = (int)(r >> 11), j = (int)(r & 2047);
            if      (which == 0) g_be0[j] = ebih0[j] + ebhh0[j];
            else if (which == 1) g_be1[j] = ebih1[j] + ebhh1[j];
            else if (which == 2) g_bd0[j] = dbih0[j] + dbhh0[j];
            else                 g_bd1[j] = dbih1[j] + dbhh1[j];
            continue;
        } r -= 8192;
        if (r < 1048576) {  // x [B,T,IN] -> [T,B,IN] fp16
            int t = (int)(r >> 13); int rem = (int)(r & 8191);
            int b = rem >> 6; int k = rem & 63;
            g_x16[r] = __float2half(x[(size_t)b * TT * INP + (size_t)t * INP + k]);
            continue;
        } r -= 1048576;
        if (r < 262144) {   // zero parity-1 h buffers (read at t=0)
            int which = (int)(r >> 16); int j = (int)(r & 65535);
            __half z = __float2half(0.f);
            if      (which == 0) g_h0[1][j]  = z;
            else if (which == 1) g_h1[1][j]  = z;
            else if (which == 2) g_hd0[1][j] = z;
            else                 g_hd1[1][j] = z;
            continue;
        } r -= 262144;
        {                   // reset grid barrier (129 words)
            if (r < NCTA) g_arrive[r] = 0u;
            else          g_gen = 0u;
        }
    }
}

// ---------------- grid barrier (all 128 CTAs resident) ----------------
__device__ __forceinline__ void grid_sync(unsigned gen) {
    int cta = blockIdx.x, tid = threadIdx.x;
    __syncthreads();
    if (tid == 0) { __threadfence(); g_arrive[cta] = gen; }
    if (cta == 0) {
        if (tid < NCTA) { while (g_arrive[tid] < gen) __nanosleep(20); }
        __syncthreads();
        if (tid == 0) g_gen = gen;
    }
    if (tid == 0) {
        while (g_gen < gen) __nanosleep(20);
        __threadfence();   // gpu-scope fence: invalidates this SM's L1D (stale h lines)
    }
    __syncthreads();
}

// ---------------- smem helpers ----------------
__device__ __forceinline__ void load_weights(__half* dst, const __half* __restrict__ W,
                                             int K, int n0) {
    int vec = K >> 3;  // uint4 per row
    for (int idx = threadIdx.x; idx < 64 * vec; idx += 256) {
        int r = idx / vec, kc = idx - r * vec;
        int grow = ((r >> 4) << 9) + n0 + (r & 15);  // g*512 + n0 + unit
        ((uint4*)(dst + r * WLD))[kc] = ((const uint4*)(W + (size_t)grow * K))[kc];
    }
}

__device__ __forceinline__ void fill_add_bias(float* smadd, const float* __restrict__ bias,
                                              int n0) {
    for (int idx = threadIdx.x; idx < 4096; idx += 256) {
        int c = idx & 63;
        smadd[idx] = bias[((c >> 4) << 9) + n0 + (c & 15)];
    }
}

__device__ __forceinline__ void fill_add_gx(float* smadd, const float* __restrict__ bias,
                                            const float* __restrict__ gx, int m0, int n0) {
    for (int idx = threadIdx.x; idx < 4096; idx += 256) {
        int m = idx >> 6, c = idx & 63;
        int col = ((c >> 4) << 9) + n0 + (c & 15);
        smadd[idx] = bias[col] + gx[(size_t)(m0 + m) * G4 + col];
    }
}

__device__ __forceinline__ void zero_smc(float* smc) {
    for (int idx = threadIdx.x; idx < 1024; idx += 256) smc[idx] = 0.f;
}

__device__ __forceinline__ float sigf(float v) { return 1.f / (1.f + __expf(-v)); }

// ---------------- one LSTM cell step (CTA tile 64 batch x 64 gate-cols) ----------------
__device__ __forceinline__ void cell_step(
    const __half* __restrict__ x, int ldx, int Kx, const __half* __restrict__ smWih,
    const __half* __restrict__ hin, const __half* __restrict__ smWhh,
    float* __restrict__ smf, const float* __restrict__ smadd, float* __restrict__ smc,
    __half* __restrict__ hout, __half* __restrict__ hsave,
    int m0, int n0)
{
    int w  = threadIdx.x >> 5;
    int kw = w & 1, mi = (w >> 1) & 1, ni = w >> 2;   // 2(k-split) x 2(m) x 2(n)

    wmma::fragment<wmma::accumulator, 16, 16, 16, float> acc[2][2];
#pragma unroll
    for (int i = 0; i < 2; i++)
#pragma unroll
        for (int j = 0; j < 2; j++) wmma::fill_fragment(acc[i][j], 0.f);
    wmma::fragment<wmma::matrix_a, 16, 16, 16, __half, wmma::row_major> af[2];
    wmma::fragment<wmma::matrix_b, 16, 16, 16, __half, wmma::col_major> bf[2];

    if (x) {
        const __half* ap = x + (size_t)(m0 + mi * 32) * ldx;
        const __half* bp = smWih + (ni * 32) * WLD;
#pragma unroll 2
        for (int k0 = kw * 16; k0 < Kx; k0 += 32) {
            wmma::load_matrix_sync(af[0], ap + k0, ldx);
            wmma::load_matrix_sync(af[1], ap + (size_t)16 * ldx + k0, ldx);
            wmma::load_matrix_sync(bf[0], bp + k0, WLD);
            wmma::load_matrix_sync(bf[1], bp + 16 * WLD + k0, WLD);
#pragma unroll
            for (int i = 0; i < 2; i++)
#pragma unroll
                for (int j = 0; j < 2; j++)
                    wmma::mma_sync(acc[i][j], af[i], bf[j], acc[i][j]);
        }
    }
    {
        const __half* ap = hin + (size_t)(m0 + mi * 32) * HID;
        const __half* bp = smWhh + (ni * 32) * WLD;
#pragma unroll 4
        for (int k0 = kw * 16; k0 < HID; k0 += 32) {
            wmma::load_matrix_sync(af[0], ap + k0, HID);
            wmma::load_matrix_sync(af[1], ap + (size_t)16 * HID + k0, HID);
            wmma::load_matrix_sync(bf[0], bp + k0, WLD);
            wmma::load_matrix_sync(bf[1], bp + 16 * WLD + k0, WLD);
#pragma unroll
            for (int i = 0; i < 2; i++)
#pragma unroll
                for (int j = 0; j < 2; j++)
                    wmma::mma_sync(acc[i][j], af[i], bf[j], acc[i][j]);
        }
    }

    float* sf = smf + kw * 4096 + (mi * 32) * 64 + ni * 32;
    wmma::store_matrix_sync(sf,            acc[0][0], 64, wmma::mem_row_major);
    wmma::store_matrix_sync(sf + 16,       acc[0][1], 64, wmma::mem_row_major);
    wmma::store_matrix_sync(sf + 16 * 64,  acc[1][0], 64, wmma::mem_row_major);
    wmma::store_matrix_sync(sf + 16 * 64 + 16, acc[1][1], 64, wmma::mem_row_major);
    __syncthreads();

    for (int idx = threadIdx.x; idx < 1024; idx += 256) {
        int m = idx >> 4, n = idx & 15;
        int r = m * 64 + n;
        float vi = smf[r]      + smf[4096 + r]      + smadd[r];
        float vf = smf[r + 16] + smf[4096 + r + 16] + smadd[r + 16];
        float vg = smf[r + 32] + smf[4096 + r + 32] + smadd[r + 32];
        float vo = smf[r + 48] + smf[4096 + r + 48] + smadd[r + 48];
        float c0 = smc[idx];
        float cn = sigf(vf) * c0 + sigf(vi) * tanhf(vg);
        float h  = sigf(vo) * tanhf(cn);
        smc[idx] = cn;
        __half hh = __float2half(h);
        size_t off = (size_t)(m0 + m) * HID + n0 + n;
        hout[off] = hh;
        if (hsave) hsave[off] = hh;
    }
}

// ---------------- persistent wavefront kernel ----------------
__global__ __launch_bounds__(256, 1) void lstm_persistent() {
    extern __shared__ char smraw[];
    __half* smWih = (__half*)smraw;
    __half* smWhh = smWih + 64 * WLD;
    float*  smf   = (float*)(smraw + 135168);
    float*  smadd = smf + 8192;
    float*  smc   = smadd + 4096;

    int cta = blockIdx.x;
    int lb  = cta & 63;
    int m0  = (lb >> 5) * 64;
    int n0  = (lb & 31) * 16;
    bool top = cta >= 64;          // layer-1 role
    unsigned gen = 0;

    // ---- encoder phase ----
    if (!top) {
        load_weights(smWih, g_eWih0, INP, n0);
        load_weights(smWhh, g_eWhh0, HID, n0);
        fill_add_bias(smadd, g_be0, n0);
    } else {
        load_weights(smWih, g_eWih1, HID, n0);
        load_weights(smWhh, g_eWhh1, HID, n0);
        fill_add_bias(smadd, g_be1, n0);
    }
    zero_smc(smc);
    __syncthreads();

    for (int s = 0; s <= TT; ++s) {
        if (!top) {
            if (s < TT)
                cell_step(g_x16 + (size_t)s * BSZ * INP, INP, INP, smWih,
                          g_h0[(s + 1) & 1], smWhh, smf, smadd, smc,
                          g_h0[s & 1], nullptr, m0, n0);
        } else {
            int t = s - 1;
            if (t >= 0)
                cell_step(g_h0[t & 1], HID, HID, smWih,
                          g_h1[(t + 1) & 1], smWhh, smf, smadd, smc,
                          g_h1[t & 1], nullptr, m0, n0);
        }
        grid_sync(++gen);
    }

    // ---- gx = z @ dWih0^T  (z = encoder h1 @ t=127, parity 1) ----
    {
        int w = threadIdx.x >> 5;
        wmma::fragment<wmma::accumulator, 16, 16, 16, float> acc1;
        wmma::fill_fragment(acc1, 0.f);
        wmma::fragment<wmma::matrix_a, 16, 16, 16, __half, wmma::row_major> af;
        wmma::fragment<wmma::matrix_b, 16, 16, 16, __half, wmma::col_major> bf;
        const __half* ap = g_h1[1] + (size_t)(w * 16) * HID;
        const __half* bp = g_dWih0 + (size_t)(cta * 16) * HID;
#pragma unroll 4
        for (int k0 = 0; k0 < HID; k0 += 16) {
            wmma::load_matrix_sync(af, ap + k0, HID);
            wmma::load_matrix_sync(bf, bp + k0, HID);
            wmma::mma_sync(acc1, af, bf, acc1);
        }
        wmma::store_matrix_sync(g_gx + (size_t)(w * 16) * G4 + cta * 16, acc1,
                                G4, wmma::mem_row_major);
    }
    grid_sync(++gen);

    // ---- decoder phase ----
    if (!top) {
        load_weights(smWhh, g_dWhh0, HID, n0);
        fill_add_gx(smadd, g_bd0, g_gx, m0, n0);   // bias + constant-input gates
    } else {
        load_weights(smWih, g_dWih1, HID, n0);
        load_weights(smWhh, g_dWhh1, HID, n0);
        fill_add_bias(smadd, g_bd1, n0);
    }
    zero_smc(smc);
    __syncthreads();

    for (int s = 0; s <= TT; ++s) {
        if (!top) {
            if (s < TT)
                cell_step(nullptr, 0, 0, nullptr,
                          g_hd0[(s + 1) & 1], smWhh, smf, smadd, smc,
                          g_hd0[s & 1], nullptr, m0, n0);
        } else {
            int t = s - 1;
            if (t >= 0)
                cell_step(g_hd0[t & 1], HID, HID, smWih,
                          g_hd1[(t + 1) & 1], smWhh, smf, smadd, smc,
                          g_hd1[t & 1], g_hs + (size_t)t * BSZ * HID, m0, n0);
        }
        grid_sync(++gen);
    }
}

// ---------------- FC head ----------------
__global__ __launch_bounds__(128) void fc_kernel(const float* __restrict__ fcb,
                                                 float* __restrict__ out) {
    int m0 = blockIdx.x * 64;           // m = t*B + b
    int w = threadIdx.x >> 5;

    wmma::fragment<wmma::accumulator, 16, 16, 16, float> acc[4];
#pragma unroll
    for (int mt = 0; mt < 4; mt++) wmma::fill_fragment(acc[mt], 0.f);
    wmma::fragment<wmma::matrix_a, 16, 16, 16, __half, wmma::row_major> af;
    wmma::fragment<wmma::matrix_b, 16, 16, 16, __half, wmma::col_major> bf;

    const __half* Wb = g_fcW + (size_t)(w * 16) * HID;
    for (int k0 = 0; k0 < HID; k0 += 16) {
        wmma::load_matrix_sync(bf, Wb + k0, HID);
#pragma unroll
        for (int mt = 0; mt < 4; mt++) {
            wmma::load_matrix_sync(af, g_hs + (size_t)(m0 + mt * 16) * HID + k0, HID);
            wmma::mma_sync(acc[mt], af, bf, acc[mt]);
        }
    }

    __shared__ float sm[64][64];
#pragma unroll
    for (int mt = 0; mt < 4; mt++)
        wmma::store_matrix_sync(&sm[mt * 16][w * 16], acc[mt], 64, wmma::mem_row_major);
    __syncthreads();

    for (int idx = threadIdx.x; idx < 4096; idx += 128) {
        int m = idx >> 6, i = idx & 63;
        int gm = m0 + m;
        int b = gm & (BSZ - 1), t = gm >> 7;
        out[(size_t)b * TT * INP + (size_t)t * INP + i] = sm[m][i] + fcb[i];
    }
}

// ---------------- launch ----------------
extern "C" void kernel_launch(void* const* d_in, const int* in_sizes, int n_in,
                              void* d_out, int out_size) {
    (void)in_sizes; (void)n_in; (void)out_size;
    const float* x      = (const float*)d_in[0];
    const float* eWih0  = (const float*)d_in[1];
    const float* eWhh0  = (const float*)d_in[2];
    const float* ebih0  = (const float*)d_in[3];
    const float* ebhh0  = (const float*)d_in[4];
    const float* eWih1  = (const float*)d_in[5];
    const float* eWhh1  = (const float*)d_in[6];
    const float* ebih1  = (const float*)d_in[7];
    const float* ebhh1  = (const float*)d_in[8];
    const float* dWih0  = (const float*)d_in[9];
    const float* dWhh0  = (const float*)d_in[10];
    const float* dbih0  = (const float*)d_in[11];
    const float* dbhh0  = (const float*)d_in[12];
    const float* dWih1  = (const float*)d_in[13];
    const float* dWhh1  = (const float*)d_in[14];
    const float* dbih1  = (const float*)d_in[15];
    const float* dbhh1  = (const float*)d_in[16];
    const float* fcW    = (const float*)d_in[17];
    const float* fcb    = (const float*)d_in[18];
    float* out = (float*)d_out;

    cudaFuncSetAttribute(lstm_persistent,
                         cudaFuncAttributeMaxDynamicSharedMemorySize, SMEM_BYTES);

    prep_kernel<<<2048, 256>>>(x, eWih0, eWhh0, ebih0, ebhh0,
                               eWih1, eWhh1, ebih1, ebhh1,
                               dWih0, dWhh0, dbih0, dbhh0,
                               dWih1, dWhh1, dbih1, dbhh1, fcW);

    lstm_persistent<<<NCTA, 256, SMEM_BYTES>>>();

    fc_kernel<<<256, 128>>>(fcb, out);
}

// round 5
// speedup vs baseline: 2.4575x; 1.0292x over previous
#include <cuda_runtime.h>
#include <cuda_fp16.h>
#include <mma.h>

using namespace nvcuda;

#define BSZ 128
#define TT  128
#define INP 64
#define HID 512
#define G4  2048
#define HB  (BSZ*HID)
#define NCTA 128
#define WLD 528                 // smem weight row stride (halves)
#define SMEM_BYTES 188416

// ---------------- device state ----------------
__device__ __half g_eWih0[G4*INP];
__device__ __half g_eWhh0[G4*HID];
__device__ __half g_eWih1[G4*HID];
__device__ __half g_eWhh1[G4*HID];
__device__ __half g_dWih0[G4*HID];
__device__ __half g_dWhh0[G4*HID];
__device__ __half g_dWih1[G4*HID];
__device__ __half g_dWhh1[G4*HID];
__device__ __half g_fcW[INP*HID];
__device__ float  g_be0[G4], g_be1[G4], g_bd0[G4], g_bd1[G4];
__device__ __half g_x16[TT*BSZ*INP];
__device__ __half g_h0[2][HB], g_h1[2][HB], g_hd0[2][HB], g_hd1[2][HB];
__device__ float  g_gx[BSZ*G4];
__device__ __half g_hs[TT*BSZ*HID];
__device__ unsigned g_ctr;

// ---------------- prep ----------------
__global__ void prep_kernel(
    const float* __restrict__ x,
    const float* __restrict__ eWih0, const float* __restrict__ eWhh0,
    const float* __restrict__ ebih0, const float* __restrict__ ebhh0,
    const float* __restrict__ eWih1, const float* __restrict__ eWhh1,
    const float* __restrict__ ebih1, const float* __restrict__ ebhh1,
    const float* __restrict__ dWih0, const float* __restrict__ dWhh0,
    const float* __restrict__ dbih0, const float* __restrict__ dbhh0,
    const float* __restrict__ dWih1, const float* __restrict__ dWhh1,
    const float* __restrict__ dbih1, const float* __restrict__ dbhh1,
    const float* __restrict__ fcW)
{
    const long NP = 8822785;
    long stride = (long)gridDim.x * blockDim.x;
    for (long i = (long)blockIdx.x * blockDim.x + threadIdx.x; i < NP; i += stride) {
        long r = i;
        if (r < 131072)  { g_eWih0[r] = __float2half(eWih0[r]); continue; } r -= 131072;
        if (r < 1048576) { g_eWhh0[r] = __float2half(eWhh0[r]); continue; } r -= 1048576;
        if (r < 1048576) { g_eWih1[r] = __float2half(eWih1[r]); continue; } r -= 1048576;
        if (r < 1048576) { g_eWhh1[r] = __float2half(eWhh1[r]); continue; } r -= 1048576;
        if (r < 1048576) { g_dWih0[r] = __float2half(dWih0[r]); continue; } r -= 1048576;
        if (r < 1048576) { g_dWhh0[r] = __float2half(dWhh0[r]); continue; } r -= 1048576;
        if (r < 1048576) { g_dWih1[r] = __float2half(dWih1[r]); continue; } r -= 1048576;
        if (r < 1048576) { g_dWhh1[r] = __float2half(dWhh1[r]); continue; } r -= 1048576;
        if (r < 32768)   { g_fcW[r]   = __float2half(fcW[r]);   continue; } r -= 32768;
        if (r < 8192) {
            int which = (int)(r >> 11), j = (int)(r & 2047);
            if      (which == 0) g_be0[j] = ebih0[j] + ebhh0[j];
            else if (which == 1) g_be1[j] = ebih1[j] + ebhh1[j];
            else if (which == 2) g_bd0[j] = dbih0[j] + dbhh0[j];
            else                 g_bd1[j] = dbih1[j] + dbhh1[j];
            continue;
        } r -= 8192;
        if (r < 1048576) {  // x [B,T,IN] -> [T,B,IN] fp16
            int t = (int)(r >> 13); int rem = (int)(r & 8191);
            int b = rem >> 6; int k = rem & 63;
            g_x16[r] = __float2half(x[(size_t)b * TT * INP + (size_t)t * INP + k]);
            continue;
        } r -= 1048576;
        if (r < 262144) {   // zero parity-1 h buffers (read at t=0)
            int which = (int)(r >> 16); int j = (int)(r & 65535);
            __half z = __float2half(0.f);
            if      (which == 0) g_h0[1][j]  = z;
            else if (which == 1) g_h1[1][j]  = z;
            else if (which == 2) g_hd0[1][j] = z;
            else                 g_hd1[1][j] = z;
            continue;
        } r -= 262144;
        g_ctr = 0u;        // barrier counter reset (graph replays)
    }
}

// ---------------- grid barrier: monotonic atomic counter ----------------
__device__ __forceinline__ void grid_sync(unsigned target) {
    __syncthreads();
    if (threadIdx.x == 0) {
        __threadfence();
        atomicAdd(&g_ctr, 1u);
        while (*((volatile unsigned*)&g_ctr) < target) { }
        __threadfence();   // gpu-scope: invalidate stale L1 h lines
    }
    __syncthreads();
}

// ---------------- smem helpers ----------------
__device__ __forceinline__ void load_weights(__half* dst, const __half* __restrict__ W,
                                             int K, int n0) {
    int vec = K >> 3;
    for (int idx = threadIdx.x; idx < 64 * vec; idx += 256) {
        int r = idx / vec, kc = idx - r * vec;
        int grow = ((r >> 4) << 9) + n0 + (r & 15);
        ((uint4*)(dst + r * WLD))[kc] = ((const uint4*)(W + (size_t)grow * K))[kc];
    }
}

__device__ __forceinline__ void fill_add_bias(float* smadd, const float* __restrict__ bias,
                                              int n0) {
    for (int idx = threadIdx.x; idx < 4096; idx += 256) {
        int c = idx & 63;
        smadd[idx] = bias[((c >> 4) << 9) + n0 + (c & 15)];
    }
}

__device__ __forceinline__ void fill_add_gx(float* smadd, const float* __restrict__ bias,
                                            const float* __restrict__ gx, int m0, int n0) {
    for (int idx = threadIdx.x; idx < 4096; idx += 256) {
        int m = idx >> 6, c = idx & 63;
        int col = ((c >> 4) << 9) + n0 + (c & 15);
        smadd[idx] = bias[col] + gx[(size_t)(m0 + m) * G4 + col];
    }
}

__device__ __forceinline__ void zero_smc(float* smc) {
    for (int idx = threadIdx.x; idx < 1024; idx += 256) smc[idx] = 0.f;
}

__device__ __forceinline__ float sigf(float v) { return 1.f / (1.f + __expf(-v)); }

// ---------------- one LSTM cell step, 3-stage software-pipelined ----------------
// CTA tile: 64 batch x 64 gate-cols.  Warps: 2(k-split) x 2(m) x 2(n).
__device__ __forceinline__ void cell_step(
    const __half* __restrict__ x, int ldx, int nx, const __half* __restrict__ smWih,
    const __half* __restrict__ hin, const __half* __restrict__ smWhh,
    float* __restrict__ smf, const float* __restrict__ smadd, float* __restrict__ smc,
    __half* __restrict__ hout, __half* __restrict__ hsave,
    int m0, int n0)
{
    int w  = threadIdx.x >> 5;
    int kw = w & 1, mi = (w >> 1) & 1, ni = w >> 2;
    const int nh = HID / 32;       // 16
    const int nit = nx + nh;

    const __half* ax = x   ? x   + (size_t)(m0 + mi * 32) * ldx : (const __half*)0;
    const __half* ah = hin + (size_t)(m0 + mi * 32) * HID;
    const __half* bx = smWih ? smWih + (ni * 32) * WLD : (const __half*)0;
    const __half* bh = smWhh + (ni * 32) * WLD;

    wmma::fragment<wmma::accumulator, 16, 16, 16, float> acc[2][2];
#pragma unroll
    for (int i = 0; i < 2; i++)
#pragma unroll
        for (int j = 0; j < 2; j++) wmma::fill_fragment(acc[i][j], 0.f);

    wmma::fragment<wmma::matrix_a, 16, 16, 16, __half, wmma::row_major> afA[2], afB[2], afC[2];
    wmma::fragment<wmma::matrix_b, 16, 16, 16, __half, wmma::col_major> bfA[2], bfB[2], bfC[2];

#define LOADF(I, AF, BF) do {                                                   \
    int _i = (I);                                                               \
    const __half *_a, *_b; int _lda;                                            \
    if (_i < nx) { int _k = kw*16 + _i*32; _a = ax + _k; _lda = ldx; _b = bx + _k; } \
    else { int _k = kw*16 + (_i-nx)*32; _a = ah + _k; _lda = HID; _b = bh + _k; } \
    wmma::load_matrix_sync(AF[0], _a, _lda);                                    \
    wmma::load_matrix_sync(AF[1], _a + (size_t)16 * _lda, _lda);                \
    wmma::load_matrix_sync(BF[0], _b, WLD);                                     \
    wmma::load_matrix_sync(BF[1], _b + 16 * WLD, WLD);                          \
} while (0)

#define MMA4(AF, BF) do {                                                       \
    wmma::mma_sync(acc[0][0], AF[0], BF[0], acc[0][0]);                         \
    wmma::mma_sync(acc[0][1], AF[0], BF[1], acc[0][1]);                         \
    wmma::mma_sync(acc[1][0], AF[1], BF[0], acc[1][0]);                         \
    wmma::mma_sync(acc[1][1], AF[1], BF[1], acc[1][1]);                         \
} while (0)

    LOADF(0, afA, bfA);
    if (1 < nit) LOADF(1, afB, bfB);
    for (int i = 0; i < nit; i += 3) {
        if (i + 2 < nit) LOADF(i + 2, afC, bfC);
        MMA4(afA, bfA);
        if (i + 3 < nit) LOADF(i + 3, afA, bfA);
        if (i + 1 < nit) MMA4(afB, bfB);
        if (i + 4 < nit) LOADF(i + 4, afB, bfB);
        if (i + 2 < nit) MMA4(afC, bfC);
    }
#undef LOADF
#undef MMA4

    float* sf = smf + kw * 4096 + (mi * 32) * 64 + ni * 32;
    wmma::store_matrix_sync(sf,                acc[0][0], 64, wmma::mem_row_major);
    wmma::store_matrix_sync(sf + 16,           acc[0][1], 64, wmma::mem_row_major);
    wmma::store_matrix_sync(sf + 16 * 64,      acc[1][0], 64, wmma::mem_row_major);
    wmma::store_matrix_sync(sf + 16 * 64 + 16, acc[1][1], 64, wmma::mem_row_major);
    __syncthreads();

    for (int idx = threadIdx.x; idx < 1024; idx += 256) {
        int m = idx >> 4, n = idx & 15;
        int r = m * 64 + n;
        float vi = smf[r]      + smf[4096 + r]      + smadd[r];
        float vf = smf[r + 16] + smf[4096 + r + 16] + smadd[r + 16];
        float vg = smf[r + 32] + smf[4096 + r + 32] + smadd[r + 32];
        float vo = smf[r + 48] + smf[4096 + r + 48] + smadd[r + 48];
        float c0 = smc[idx];
        float cn = sigf(vf) * c0 + sigf(vi) * tanhf(vg);
        float h  = sigf(vo) * tanhf(cn);
        smc[idx] = cn;
        __half hh = __float2half(h);
        size_t off = (size_t)(m0 + m) * HID + n0 + n;
        hout[off] = hh;
        if (hsave) hsave[off] = hh;
    }
}

// ---------------- persistent wavefront kernel ----------------
__global__ __launch_bounds__(256, 1) void lstm_persistent() {
    extern __shared__ char smraw[];
    __half* smWih = (__half*)smraw;
    __half* smWhh = smWih + 64 * WLD;
    float*  smf   = (float*)(smraw + 135168);
    float*  smadd = smf + 8192;
    float*  smc   = smadd + 4096;

    int cta = blockIdx.x;
    int lb  = cta & 63;
    int m0  = (lb >> 5) * 64;
    int n0  = (lb & 31) * 16;
    bool top = cta >= 64;
    unsigned gen = 0;

    // ---- encoder ----
    if (!top) {
        load_weights(smWih, g_eWih0, INP, n0);
        load_weights(smWhh, g_eWhh0, HID, n0);
        fill_add_bias(smadd, g_be0, n0);
    } else {
        load_weights(smWih, g_eWih1, HID, n0);
        load_weights(smWhh, g_eWhh1, HID, n0);
        fill_add_bias(smadd, g_be1, n0);
    }
    zero_smc(smc);
    __syncthreads();

    for (int s = 0; s <= TT; ++s) {
        if (!top) {
            if (s < TT)
                cell_step(g_x16 + (size_t)s * BSZ * INP, INP, INP / 32, smWih,
                          g_h0[(s + 1) & 1], smWhh, smf, smadd, smc,
                          g_h0[s & 1], nullptr, m0, n0);
        } else {
            int t = s - 1;
            if (t >= 0)
                cell_step(g_h0[t & 1], HID, HID / 32, smWih,
                          g_h1[(t + 1) & 1], smWhh, smf, smadd, smc,
                          g_h1[t & 1], nullptr, m0, n0);
        }
        grid_sync(++gen * NCTA);
    }

    // ---- gx = z @ dWih0^T ----
    {
        int w = threadIdx.x >> 5;
        wmma::fragment<wmma::accumulator, 16, 16, 16, float> acc1;
        wmma::fill_fragment(acc1, 0.f);
        wmma::fragment<wmma::matrix_a, 16, 16, 16, __half, wmma::row_major> af;
        wmma::fragment<wmma::matrix_b, 16, 16, 16, __half, wmma::col_major> bf;
        const __half* ap = g_h1[1] + (size_t)(w * 16) * HID;
        const __half* bp = g_dWih0 + (size_t)(cta * 16) * HID;
#pragma unroll 4
        for (int k0 = 0; k0 < HID; k0 += 16) {
            wmma::load_matrix_sync(af, ap + k0, HID);
            wmma::load_matrix_sync(bf, bp + k0, HID);
            wmma::mma_sync(acc1, af, bf, acc1);
        }
        wmma::store_matrix_sync(g_gx + (size_t)(w * 16) * G4 + cta * 16, acc1,
                                G4, wmma::mem_row_major);
    }
    grid_sync(++gen * NCTA);

    // ---- decoder ----
    if (!top) {
        load_weights(smWhh, g_dWhh0, HID, n0);
        fill_add_gx(smadd, g_bd0, g_gx, m0, n0);
    } else {
        load_weights(smWih, g_dWih1, HID, n0);
        load_weights(smWhh, g_dWhh1, HID, n0);
        fill_add_bias(smadd, g_bd1, n0);
    }
    zero_smc(smc);
    __syncthreads();

    for (int s = 0; s <= TT; ++s) {
        if (!top) {
            if (s < TT)
                cell_step(nullptr, 0, 0, nullptr,
                          g_hd0[(s + 1) & 1], smWhh, smf, smadd, smc,
                          g_hd0[s & 1], nullptr, m0, n0);
        } else {
            int t = s - 1;
            if (t >= 0)
                cell_step(g_hd0[t & 1], HID, HID / 32, smWih,
                          g_hd1[(t + 1) & 1], smWhh, smf, smadd, smc,
                          g_hd1[t & 1], g_hs + (size_t)t * BSZ * HID, m0, n0);
        }
        grid_sync(++gen * NCTA);
    }
}

// ---------------- FC head ----------------
__global__ __launch_bounds__(128) void fc_kernel(const float* __restrict__ fcb,
                                                 float* __restrict__ out) {
    int m0 = blockIdx.x * 64;
    int w = threadIdx.x >> 5;

    wmma::fragment<wmma::accumulator, 16, 16, 16, float> acc[4];
#pragma unroll
    for (int mt = 0; mt < 4; mt++) wmma::fill_fragment(acc[mt], 0.f);
    wmma::fragment<wmma::matrix_a, 16, 16, 16, __half, wmma::row_major> af;
    wmma::fragment<wmma::matrix_b, 16, 16, 16, __half, wmma::col_major> bf;

    const __half* Wb = g_fcW + (size_t)(w * 16) * HID;
    for (int k0 = 0; k0 < HID; k0 += 16) {
        wmma::load_matrix_sync(bf, Wb + k0, HID);
#pragma unroll
        for (int mt = 0; mt < 4; mt++) {
            wmma::load_matrix_sync(af, g_hs + (size_t)(m0 + mt * 16) * HID + k0, HID);
            wmma::mma_sync(acc[mt], af, bf, acc[mt]);
        }
    }

    __shared__ float sm[64][64];
#pragma unroll
    for (int mt = 0; mt < 4; mt++)
        wmma::store_matrix_sync(&sm[mt * 16][w * 16], acc[mt], 64, wmma::mem_row_major);
    __syncthreads();

    for (int idx = threadIdx.x; idx < 4096; idx += 128) {
        int m = idx >> 6, i = idx & 63;
        int gm = m0 + m;
        int b = gm & (BSZ - 1), t = gm >> 7;
        out[(size_t)b * TT * INP + (size_t)t * INP + i] = sm[m][i] + fcb[i];
    }
}

// ---------------- launch ----------------
extern "C" void kernel_launch(void* const* d_in, const int* in_sizes, int n_in,
                              void* d_out, int out_size) {
    (void)in_sizes; (void)n_in; (void)out_size;
    const float* x      = (const float*)d_in[0];
    const float* eWih0  = (const float*)d_in[1];
    const float* eWhh0  = (const float*)d_in[2];
    const float* ebih0  = (const float*)d_in[3];
    const float* ebhh0  = (const float*)d_in[4];
    const float* eWih1  = (const float*)d_in[5];
    const float* eWhh1  = (const float*)d_in[6];
    const float* ebih1  = (const float*)d_in[7];
    const float* ebhh1  = (const float*)d_in[8];
    const float* dWih0  = (const float*)d_in[9];
    const float* dWhh0  = (const float*)d_in[10];
    const float* dbih0  = (const float*)d_in[11];
    const float* dbhh0  = (const float*)d_in[12];
    const float* dWih1  = (const float*)d_in[13];
    const float* dWhh1  = (const float*)d_in[14];
    const float* dbih1  = (const float*)d_in[15];
    const float* dbhh1  = (const float*)d_in[16];
    const float* fcW    = (const float*)d_in[17];
    const float* fcb    = (const float*)d_in[18];
    float* out = (float*)d_out;

    cudaFuncSetAttribute(lstm_persistent,
                         cudaFuncAttributeMaxDynamicSharedMemorySize, SMEM_BYTES);

    prep_kernel<<<2048, 256>>>(x, eWih0, eWhh0, ebih0, ebhh0,
                               eWih1, eWhh1, ebih1, ebhh1,
                               dWih0, dWhh0, dbih0, dbhh0,
                               dWih1, dWhh1, dbih1, dbhh1, fcW);

    lstm_persistent<<<NCTA, 256, SMEM_BYTES>>>();

    fc_kernel<<<256, 128>>>(fcb, out);
}

// round 8
// speedup vs baseline: 4.1235x; 1.6779x over previous
#include <cstdint>
#include <cstddef>
#include <cuda_runtime.h>
#include <cuda_fp16.h>
#include <mma.h>

using namespace nvcuda;

#define BSZ 128
#define TT  128
#define INP 64
#define HID 512
#define G4  2048
#define HB  (BSZ*HID)
#define NCTA 128

// dynamic smem map (bytes):
//   [0, 132096)        weights: 64 rows x 1032 halves (stride 2064 B)
//   [132096, 165888)   A buffer 0: 64 rows x 264 halves (stride 528 B)
//   [165888, 199680)   A buffer 1
//   [199680, 216064)   smf: 64x64 float
#define WSTRH   1032
#define WSTRB   2064
#define ASTRH   264
#define ASTRB   528
#define ABUF0   132096
#define ABSZ    33792
#define SMFOFF  199680
#define SMEM_TOTAL 216064

// ---------------- device state ----------------
__device__ __align__(128) __half g_eWih0[G4*INP];
__device__ __align__(128) __half g_eWhh0[G4*HID];
__device__ __align__(128) __half g_eWih1[G4*HID];
__device__ __align__(128) __half g_eWhh1[G4*HID];
__device__ __align__(128) __half g_dWih0[G4*HID];
__device__ __align__(128) __half g_dWhh0[G4*HID];
__device__ __align__(128) __half g_dWih1[G4*HID];
__device__ __align__(128) __half g_dWhh1[G4*HID];
__device__ __align__(128) __half g_fcW[INP*HID];
__device__ float  g_be0[G4];
__device__ float  g_be1[G4];
__device__ float  g_bd0[G4];
__device__ float  g_bd1[G4];
__device__ __align__(128) __half g_x16[TT*BSZ*INP];
__device__ __align__(128) __half g_h0[2][HB];
__device__ __align__(128) __half g_h1[2][HB];
__device__ __align__(128) __half g_hd0[2][HB];
__device__ __align__(128) __half g_hd1[2][HB];
__device__ float  g_gx[BSZ*G4];
__device__ __align__(128) __half g_hs[TT*BSZ*HID];
__device__ unsigned g_ctr;

// ---------------- prep ----------------
__global__ void prep_kernel(
    const float* __restrict__ x,
    const float* __restrict__ eWih0, const float* __restrict__ eWhh0,
    const float* __restrict__ ebih0, const float* __restrict__ ebhh0,
    const float* __restrict__ eWih1, const float* __restrict__ eWhh1,
    const float* __restrict__ ebih1, const float* __restrict__ ebhh1,
    const float* __restrict__ dWih0, const float* __restrict__ dWhh0,
    const float* __restrict__ dbih0, const float* __restrict__ dbhh0,
    const float* __restrict__ dWih1, const float* __restrict__ dWhh1,
    const float* __restrict__ dbih1, const float* __restrict__ dbhh1,
    const float* __restrict__ fcW)
{
    const long NP = 8822785;
    long stride = (long)gridDim.x * blockDim.x;
    for (long i = (long)blockIdx.x * blockDim.x + threadIdx.x; i < NP; i += stride) {
        long r = i;
        if (r < 131072)  { g_eWih0[r] = __float2half(eWih0[r]); continue; } r -= 131072;
        if (r < 1048576) { g_eWhh0[r] = __float2half(eWhh0[r]); continue; } r -= 1048576;
        if (r < 1048576) { g_eWih1[r] = __float2half(eWih1[r]); continue; } r -= 1048576;
        if (r < 1048576) { g_eWhh1[r] = __float2half(eWhh1[r]); continue; } r -= 1048576;
        if (r < 1048576) { g_dWih0[r] = __float2half(dWih0[r]); continue; } r -= 1048576;
        if (r < 1048576) { g_dWhh0[r] = __float2half(dWhh0[r]); continue; } r -= 1048576;
        if (r < 1048576) { g_dWih1[r] = __float2half(dWih1[r]); continue; } r -= 1048576;
        if (r < 1048576) { g_dWhh1[r] = __float2half(dWhh1[r]); continue; } r -= 1048576;
        if (r < 32768)   { g_fcW[r]   = __float2half(fcW[r]);   continue; } r -= 32768;
        if (r < 8192) {
            int which = (int)(r >> 11);
            int j = (int)(r & 2047);
            if      (which == 0) g_be0[j] = ebih0[j] + ebhh0[j];
            else if (which == 1) g_be1[j] = ebih1[j] + ebhh1[j];
            else if (which == 2) g_bd0[j] = dbih0[j] + dbhh0[j];
            else                 g_bd1[j] = dbih1[j] + dbhh1[j];
            continue;
        } r -= 8192;
        if (r < 1048576) {
            int t = (int)(r >> 13);
            int rem = (int)(r & 8191);
            int b = rem >> 6;
            int k = rem & 63;
            g_x16[r] = __float2half(x[(size_t)b * TT * INP + (size_t)t * INP + k]);
            continue;
        } r -= 1048576;
        if (r < 262144) {
            int which = (int)(r >> 16);
            int j = (int)(r & 65535);
            __half z = __float2half(0.f);
            if      (which == 0) g_h0[1][j]  = z;
            else if (which == 1) g_h1[1][j]  = z;
            else if (which == 2) g_hd0[1][j] = z;
            else                 g_hd1[1][j] = z;
            continue;
        } r -= 262144;
        g_ctr = 0u;
    }
}

// ---------------- helpers ----------------
__device__ __forceinline__ uint32_t smem_to_u32(const void* smem_ptr) {
    uint32_t addr;
    asm("{ .reg .u64 tmp; cvta.to.shared.u64 tmp, %1; cvt.u32.u64 %0, tmp; }"
        : "=r"(addr) : "l"(smem_ptr));
    return addr;
}
__device__ __forceinline__ void cp_async16(uint32_t dst_smem, const void* src) {
    asm volatile("cp.async.cg.shared.global [%0], [%1], 16;"
                 :: "r"(dst_smem), "l"(src) : "memory");
}
__device__ __forceinline__ void cp_async_commit() {
    asm volatile("cp.async.commit_group;" ::: "memory");
}
__device__ __forceinline__ void cp_async_wait0() {
    asm volatile("cp.async.wait_group 0;" ::: "memory");
}
__device__ __forceinline__ void cp_async_wait1() {
    asm volatile("cp.async.wait_group 1;" ::: "memory");
}
__device__ __forceinline__ float sigf(float v) { return 1.f / (1.f + __expf(-v)); }

// ---------------- grid barrier ----------------
__device__ __forceinline__ void grid_sync(unsigned target) {
    __syncthreads();
    if (threadIdx.x == 0) {
        __threadfence();
        atomicAdd(&g_ctr, 1u);
        volatile unsigned* cp = &g_ctr;
        while (*cp < target) { }
        __threadfence();   // gpu-scope: invalidates stale L1 lines before next phase reads
    }
    __syncthreads();
}

// ---------------- stationary weight load ----------------
// smem row c (D-col c): weight row grow = (c&3)*512 + u0 + (c>>2); row = [W1 | W2]
__device__ void load_wsm(char* smraw, const __half* __restrict__ W1, int Kx,
                         const __half* __restrict__ W2, int u0) {
    int K = Kx + 512;
    int ng = K >> 3;
    int tot = 64 * ng;
    for (int idx = threadIdx.x; idx < tot; idx += 256) {
        int c = idx / ng;
        int gi = idx - c * ng;
        int k = gi << 3;
        int grow = (c & 3) * 512 + u0 + (c >> 2);
        uint4 v;
        if (k < Kx) v = *(const uint4*)(W1 + (size_t)grow * Kx + k);
        else        v = *(const uint4*)(W2 + (size_t)grow * 512 + (k - Kx));
        *(uint4*)(smraw + (size_t)c * WSTRB + ((size_t)k << 1)) = v;
    }
}

// ---------------- stage one A super-chunk [64 rows x (ke-kb) halves] ----------------
__device__ __forceinline__ void stage_chunk(uint32_t dst, int kb, int ke,
                                            const __half* __restrict__ s0, int ld0, int Kx,
                                            const __half* __restrict__ s1, int m0) {
    int ng = (ke - kb) >> 3;       // 16B granules per row: 32 or 8
    int tot = 64 * ng;
    for (int idx = threadIdx.x; idx < tot; idx += 256) {
        int r, gi;
        if (ng == 32) { r = idx >> 5; gi = idx & 31; }
        else          { r = idx >> 3; gi = idx & 7; }
        int k = kb + (gi << 3);
        const __half* src;
        if (k < Kx) src = s0 + (size_t)(m0 + r) * ld0 + k;
        else        src = s1 + (size_t)(m0 + r) * HID + (k - Kx);
        cp_async16(dst + (uint32_t)(r * ASTRB + (gi << 4)), src);
    }
}

// ---------------- one LSTM cell step (smem-staged, HMMA) ----------------
// CTA tile: 64 batch rows x 64 gate-cols (16 units x 4 gates, gate = col&3)
__device__ __forceinline__ void cell_step(
    char* smraw, uint32_t smb,
    const __half* __restrict__ s0, int ld0, int Kx,
    const __half* __restrict__ s1, int K,
    const float* badd, float* cst,
    __half* __restrict__ hout, __half* __restrict__ hsave,
    int m0, int u0, int mi, int ni, int uloc, int mb)
{
    wmma::fragment<wmma::accumulator, 16, 16, 16, float> acc0, acc1;
    wmma::fill_fragment(acc0, 0.f);
    wmma::fill_fragment(acc1, 0.f);
    wmma::fragment<wmma::matrix_a, 16, 16, 16, __half, wmma::row_major> af0, af1;
    wmma::fragment<wmma::matrix_b, 16, 16, 16, __half, wmma::col_major> bf;

    int nsc = (K + 255) >> 8;
    {
        int ke0 = (K < 256) ? K : 256;
        stage_chunk(smb + ABUF0, 0, ke0, s0, ld0, Kx, s1, m0);
        cp_async_commit();
    }
    for (int sc = 0; sc < nsc; ++sc) {
        int kb = sc << 8;
        int ke = kb + 256;
        if (ke > K) ke = K;
        if (sc + 1 < nsc) {
            int kb2 = (sc + 1) << 8;
            int ke2 = kb2 + 256;
            if (ke2 > K) ke2 = K;
            stage_chunk(smb + ABUF0 + (uint32_t)(((sc + 1) & 1) * ABSZ),
                        kb2, ke2, s0, ld0, Kx, s1, m0);
            cp_async_commit();
            cp_async_wait1();
        } else {
            cp_async_wait0();
        }
        __syncthreads();
        const __half* abase = (const __half*)(smraw + ABUF0 + (size_t)((sc & 1) * ABSZ))
                            + (size_t)(mi * 32) * ASTRH;
        const __half* bbase = (const __half*)smraw + (size_t)(ni * 16) * WSTRH + kb;
        int nslab = (ke - kb) >> 4;
#pragma unroll 4
        for (int sl = 0; sl < nslab; ++sl) {
            int kk = sl << 4;
            wmma::load_matrix_sync(af0, abase + kk, ASTRH);
            wmma::load_matrix_sync(af1, abase + 16 * ASTRH + kk, ASTRH);
            wmma::load_matrix_sync(bf, bbase + kk, WSTRH);
            wmma::mma_sync(acc0, af0, bf, acc0);
            wmma::mma_sync(acc1, af1, bf, acc1);
        }
        __syncthreads();
    }

    float* smf = (float*)(smraw + SMFOFF);
    wmma::store_matrix_sync(smf + (size_t)(mi * 32) * 64 + ni * 16, acc0, 64,
                            wmma::mem_row_major);
    wmma::store_matrix_sync(smf + (size_t)(mi * 32 + 16) * 64 + ni * 16, acc1, 64,
                            wmma::mem_row_major);
    __syncthreads();

#pragma unroll
    for (int j = 0; j < 4; ++j) {
        int m = mb + 16 * j;
        float4 gq = *(const float4*)(smf + (size_t)m * 64 + uloc * 4);
        float vi = gq.x + badd[j * 4 + 0];
        float vf = gq.y + badd[j * 4 + 1];
        float vg = gq.z + badd[j * 4 + 2];
        float vo = gq.w + badd[j * 4 + 3];
        float cn = sigf(vf) * cst[j] + sigf(vi) * tanhf(vg);
        float h  = sigf(vo) * tanhf(cn);
        cst[j] = cn;
        __half hh = __float2half(h);
        size_t off = (size_t)(m0 + m) * HID + u0 + uloc;
        hout[off] = hh;
        if (hsave) hsave[off] = hh;
    }
}

// ---------------- persistent wavefront kernel ----------------
__global__ __launch_bounds__(256, 1) void lstm_hmma() {
    extern __shared__ char smraw[];
    uint32_t smb = smem_to_u32(smraw);
    int tid = threadIdx.x;
    int w = tid >> 5;
    int cta = blockIdx.x;
    int lb = cta & 63;
    bool top = (cta >= 64);
    int m0 = (lb >> 5) * 64;
    int u0 = (lb & 31) * 16;
    int mi = w >> 2;
    int ni = w & 3;
    int uloc = tid & 15;
    int mb = tid >> 4;          // epilogue base row (0..15)

    float badd[16];
    float cst[4];
    unsigned gen = 0;

    // ===== encoder =====
    if (!top) load_wsm(smraw, g_eWih0, INP, g_eWhh0, u0);
    else      load_wsm(smraw, g_eWih1, HID, g_eWhh1, u0);
    {
        const float* bias = top ? g_be1 : g_be0;
#pragma unroll
        for (int j = 0; j < 4; ++j)
#pragma unroll
            for (int g = 0; g < 4; ++g)
                badd[j * 4 + g] = bias[g * 512 + u0 + uloc];
    }
#pragma unroll
    for (int j = 0; j < 4; ++j) cst[j] = 0.f;
    __syncthreads();

    for (int s = 0; s <= TT; ++s) {
        if (!top) {
            if (s < TT)
                cell_step(smraw, smb, g_x16 + (size_t)s * BSZ * INP, INP, INP,
                          g_h0[(s + 1) & 1], INP + HID, badd, cst,
                          g_h0[s & 1], (__half*)0, m0, u0, mi, ni, uloc, mb);
        } else {
            int t = s - 1;
            if (t >= 0)
                cell_step(smraw, smb, g_h0[t & 1], HID, HID,
                          g_h1[(t + 1) & 1], 2 * HID, badd, cst,
                          g_h1[t & 1], (__half*)0, m0, u0, mi, ni, uloc, mb);
        }
        gen++;
        grid_sync(gen * NCTA);
    }

    // ===== gx = z @ dWih0^T (one-off; z = encoder h1 at t=127, parity 1) =====
    {
        wmma::fragment<wmma::accumulator, 16, 16, 16, float> acc1;
        wmma::fill_fragment(acc1, 0.f);
        wmma::fragment<wmma::matrix_a, 16, 16, 16, __half, wmma::row_major> af;
        wmma::fragment<wmma::matrix_b, 16, 16, 16, __half, wmma::col_major> bfx;
        const __half* ap = g_h1[1] + (size_t)(w * 16) * HID;
        const __half* bp = g_dWih0 + (size_t)(cta * 16) * HID;
#pragma unroll 4
        for (int k0 = 0; k0 < HID; k0 += 16) {
            wmma::load_matrix_sync(af, ap + k0, HID);
            wmma::load_matrix_sync(bfx, bp + k0, HID);
            wmma::mma_sync(acc1, af, bfx, acc1);
        }
        wmma::store_matrix_sync(g_gx + (size_t)(w * 16) * G4 + cta * 16, acc1,
                                G4, wmma::mem_row_major);
    }
    gen++;
    grid_sync(gen * NCTA);

    // ===== decoder =====
    if (!top) {
        load_wsm(smraw, (const __half*)0, 0, g_dWhh0, u0);
#pragma unroll
        for (int j = 0; j < 4; ++j)
#pragma unroll
            for (int g = 0; g < 4; ++g) {
                int colg = g * 512 + u0 + uloc;
                badd[j * 4 + g] = g_bd0[colg]
                                + g_gx[(size_t)(m0 + mb + 16 * j) * G4 + colg];
            }
    } else {
        load_wsm(smraw, g_dWih1, HID, g_dWhh1, u0);
#pragma unroll
        for (int j = 0; j < 4; ++j)
#pragma unroll
            for (int g = 0; g < 4; ++g)
                badd[j * 4 + g] = g_bd1[g * 512 + u0 + uloc];
    }
#pragma unroll
    for (int j = 0; j < 4; ++j) cst[j] = 0.f;
    __syncthreads();

    for (int s = 0; s <= TT; ++s) {
        if (!top) {
            if (s < TT)
                cell_step(smraw, smb, (const __half*)0, 0, 0,
                          g_hd0[(s + 1) & 1], HID, badd, cst,
                          g_hd0[s & 1], (__half*)0, m0, u0, mi, ni, uloc, mb);
        } else {
            int t = s - 1;
            if (t >= 0)
                cell_step(smraw, smb, g_hd0[t & 1], HID, HID,
                          g_hd1[(t + 1) & 1], 2 * HID, badd, cst,
                          g_hd1[t & 1], g_hs + (size_t)t * BSZ * HID,
                          m0, u0, mi, ni, uloc, mb);
        }
        gen++;
        grid_sync(gen * NCTA);
    }
}

// ---------------- FC head ----------------
__global__ __launch_bounds__(128) void fc_kernel(const float* __restrict__ fcb,
                                                 float* __restrict__ out) {
    int m0 = blockIdx.x * 64;
    int w = threadIdx.x >> 5;

    wmma::fragment<wmma::accumulator, 16, 16, 16, float> acc[4];
#pragma unroll
    for (int mt = 0; mt < 4; mt++) wmma::fill_fragment(acc[mt], 0.f);
    wmma::fragment<wmma::matrix_a, 16, 16, 16, __half, wmma::row_major> af;
    wmma::fragment<wmma::matrix_b, 16, 16, 16, __half, wmma::col_major> bf;

    const __half* Wb = g_fcW + (size_t)(w * 16) * HID;
    for (int k0 = 0; k0 < HID; k0 += 16) {
        wmma::load_matrix_sync(bf, Wb + k0, HID);
#pragma unroll
        for (int mt = 0; mt < 4; mt++) {
            wmma::load_matrix_sync(af, g_hs + (size_t)(m0 + mt * 16) * HID + k0, HID);
            wmma::mma_sync(acc[mt], af, bf, acc[mt]);
        }
    }

    __shared__ float sm[64][64];
#pragma unroll
    for (int mt = 0; mt < 4; mt++) {
        wmma::store_matrix_sync(&sm[mt * 16][w * 16], acc[mt], 64, wmma::mem_row_major);
    }
    __syncthreads();

    for (int idx = threadIdx.x; idx < 4096; idx += 128) {
        int m = idx >> 6;
        int i = idx & 63;
        int gm = m0 + m;
        int b = gm & (BSZ - 1);
        int t = gm >> 7;
        out[(size_t)b * TT * INP + (size_t)t * INP + i] = sm[m][i] + fcb[i];
    }
}

// ---------------- launch ----------------
extern "C" void kernel_launch(void* const* d_in, const int* in_sizes, int n_in,
                              void* d_out, int out_size) {
    (void)in_sizes; (void)n_in; (void)out_size;
    const float* x      = (const float*)d_in[0];
    const float* eWih0  = (const float*)d_in[1];
    const float* eWhh0  = (const float*)d_in[2];
    const float* ebih0  = (const float*)d_in[3];
    const float* ebhh0  = (const float*)d_in[4];
    const float* eWih1  = (const float*)d_in[5];
    const float* eWhh1  = (const float*)d_in[6];
    const float* ebih1  = (const float*)d_in[7];
    const float* ebhh1  = (const float*)d_in[8];
    const float* dWih0  = (const float*)d_in[9];
    const float* dWhh0  = (const float*)d_in[10];
    const float* dbih0  = (const float*)d_in[11];
    const float* dbhh0  = (const float*)d_in[12];
    const float* dWih1  = (const float*)d_in[13];
    const float* dWhh1  = (const float*)d_in[14];
    const float* dbih1  = (const float*)d_in[15];
    const float* dbhh1  = (const float*)d_in[16];
    const float* fcW    = (const float*)d_in[17];
    const float* fcb    = (const float*)d_in[18];
    float* out = (float*)d_out;

    cudaFuncSetAttribute(lstm_hmma,
                         cudaFuncAttributeMaxDynamicSharedMemorySize, SMEM_TOTAL);

    prep_kernel<<<2048, 256>>>(x, eWih0, eWhh0, ebih0, ebhh0,
                               eWih1, eWhh1, ebih1, ebhh1,
                               dWih0, dWhh0, dbih0, dbhh0,
                               dWih1, dWhh1, dbih1, dbhh1, fcW);

    lstm_hmma<<<NCTA, 256, SMEM_TOTAL>>>();

    fc_kernel<<<256, 128>>>(fcb, out);
}